// round 1
// baseline (speedup 1.0000x reference)
#include <cuda_runtime.h>
#include <math.h>

#define B_DIM 32
#define T_SEQ 512
#define D_DIM 512
#define U_DIM 512
#define NG    2048                 // 4*U
#define M_TOT (B_DIM * T_SEQ)     // 16384

// ---------------- scratch (static device memory; no allocations) ----------------
__device__ float g_xg[2][B_DIM][T_SEQ][NG];        // input projections, both dirs (256 MB)
__device__ float g_hbuf[2][2][B_DIM][U_DIM];       // h double buffers per direction
__device__ float g_hb_out[B_DIM][T_SEQ][U_DIM];    // backward-direction outputs
__device__ volatile unsigned g_epoch;              // barrier epoch (monotonic across launches)
__device__ unsigned g_count;                       // barrier arrival counter (self-resetting)

#define NCTA        128
#define REC_THREADS 128
#define HS_STRIDE   516                            // 512 + 4 pad (2064B: 16B-aligned rows, bank-spread)
#define SMEM_REC    (2 * 32 * HS_STRIDE * 4)       // Us[32][516] + hs[32][516] = 132096 B

// =================================================================================
// Kernel A: xg[dir] = x @ W[dir] + b[dir]     (M=16384, K=512, N=2048, fp32 SGEMM)
// 128x128 block tile, BK=8, 8x8 per thread, 256 threads, register prefetch.
// =================================================================================
__global__ __launch_bounds__(256) void gemm_xg(
    const float* __restrict__ X,
    const float* __restrict__ Wf, const float* __restrict__ bf,
    const float* __restrict__ Wb, const float* __restrict__ bb)
{
    const int dir = blockIdx.z;
    const float* __restrict__ W    = dir ? Wb : Wf;
    const float* __restrict__ bias = dir ? bb : bf;

    __shared__ float As[8][128];   // k-major (transposed on store)
    __shared__ float Bs[8][128];

    const int tid   = threadIdx.x;
    const int mBase = blockIdx.x * 128;
    const int nBase = blockIdx.y * 128;

    const int aRow = tid >> 1;            // 0..127
    const int aK   = (tid & 1) * 4;       // 0 or 4
    const int bK   = tid >> 5;            // 0..7
    const int bN   = (tid & 31) * 4;      // 0..124

    const float* aPtr = X + (size_t)(mBase + aRow) * D_DIM + aK;
    const float* bPtr = W + (size_t)bK * NG + nBase + bN;

    float4 aReg = *(const float4*)aPtr;
    float4 bReg = *(const float4*)bPtr;

    float acc[8][8];
    #pragma unroll
    for (int i = 0; i < 8; i++)
        #pragma unroll
        for (int j = 0; j < 8; j++) acc[i][j] = 0.0f;

    const int ty = tid >> 4;    // 0..15
    const int tx = tid & 15;    // 0..15

    for (int kt = 0; kt < D_DIM; kt += 8) {
        As[aK + 0][aRow] = aReg.x;
        As[aK + 1][aRow] = aReg.y;
        As[aK + 2][aRow] = aReg.z;
        As[aK + 3][aRow] = aReg.w;
        *(float4*)&Bs[bK][bN] = bReg;
        __syncthreads();

        if (kt + 8 < D_DIM) {
            aReg = *(const float4*)(aPtr + kt + 8);
            bReg = *(const float4*)(bPtr + (size_t)(kt + 8) * NG);
        }

        #pragma unroll
        for (int k = 0; k < 8; k++) {
            float4 a0 = *(const float4*)&As[k][ty * 8];
            float4 a1 = *(const float4*)&As[k][ty * 8 + 4];
            float4 b0 = *(const float4*)&Bs[k][tx * 8];
            float4 b1 = *(const float4*)&Bs[k][tx * 8 + 4];
            float av[8] = {a0.x, a0.y, a0.z, a0.w, a1.x, a1.y, a1.z, a1.w};
            float bv[8] = {b0.x, b0.y, b0.z, b0.w, b1.x, b1.y, b1.z, b1.w};
            #pragma unroll
            for (int i = 0; i < 8; i++)
                #pragma unroll
                for (int j = 0; j < 8; j++)
                    acc[i][j] = fmaf(av[i], bv[j], acc[i][j]);
        }
        __syncthreads();
    }

    float* outp = &g_xg[dir][0][0][0];
    #pragma unroll
    for (int i = 0; i < 8; i++) {
        int m = mBase + ty * 8 + i;
        float* row = outp + (size_t)m * NG + nBase + tx * 8;
        #pragma unroll
        for (int j = 0; j < 8; j++)
            row[j] = acc[i][j] + bias[nBase + tx * 8 + j];
    }
}

// =================================================================================
// Device-wide barrier (epoch-based, self-resetting counter for graph replays)
// =================================================================================
__device__ __forceinline__ void gbar(unsigned target)
{
    __syncthreads();
    if (threadIdx.x == 0) {
        __threadfence();
        unsigned v = atomicAdd(&g_count, 1u);
        if (v == NCTA - 1u) {
            g_count = 0u;
            __threadfence();
            g_epoch = target;
        } else {
            while (g_epoch < target) { }
        }
        __threadfence();
    }
    __syncthreads();
}

__device__ __forceinline__ float sigm(float x) { return 1.0f / (1.0f + expf(-x)); }

// =================================================================================
// Kernel B: persistent bidirectional LSTM recurrence.
// 128 CTAs (64 per direction), 128 threads each. CTA owns 8 units x 32 batches.
// U slice (32 gate-cols x 512) resident in smem for the whole kernel; h re-staged
// from global each step; c kept in registers. Thread = 2 batches x 1 unit x 4 gates.
// =================================================================================
__global__ __launch_bounds__(REC_THREADS, 1) void lstm_rec(
    const float* __restrict__ z,
    const float* __restrict__ Uf, const float* __restrict__ Ub,
    float* __restrict__ out)
{
    extern __shared__ float sm[];
    float* Us = sm;                        // [32 cols][HS_STRIDE]
    float* hs = sm + 32 * HS_STRIDE;       // [32 batches][HS_STRIDE]

    const int bid = blockIdx.x;
    const int dir = bid & 1;
    const int blk = bid >> 1;              // 0..63
    const int u0  = blk * 8;
    const int tid = threadIdx.x;
    const int bp  = tid >> 3;              // 0..15
    const int uu  = tid & 7;               // 0..7
    const int b0  = bp * 2, b1 = b0 + 1;
    const int ug  = u0 + uu;
    const float* __restrict__ Uw = dir ? Ub : Uf;

    unsigned ep = g_epoch;   // all CTAs read the same stable value at launch start

    // Load U slice into smem, transposed: Us[g*8+u][k] = Uw[k][g*512 + u0 + u]
    {
        int ci = tid & 31;
        int gg = ci >> 3;
        int ul = ci & 7;
        int cg = gg * U_DIM + u0 + ul;
        int k0 = (tid >> 5) * 128;
        const float* src = Uw + cg;
        float* dst = Us + ci * HS_STRIDE;
        for (int k = k0; k < k0 + 128; k++)
            dst[k] = src[(size_t)k * NG];
    }

    // init: h0 = c0 = z
    float c0s = z[b0 * U_DIM + ug];
    float c1s = z[b1 * U_DIM + ug];
    g_hbuf[dir][0][b0][ug] = c0s;
    g_hbuf[dir][0][b1][ug] = c1s;

    gbar(++ep);

    const float* up0 = Us + (0 * 8 + uu) * HS_STRIDE;
    const float* up1 = Us + (1 * 8 + uu) * HS_STRIDE;
    const float* up2 = Us + (2 * 8 + uu) * HS_STRIDE;
    const float* up3 = Us + (3 * 8 + uu) * HS_STRIDE;

    for (int s = 0; s < T_SEQ; s++) {
        const int buf = s & 1;

        // stage h (this direction) into smem
        const float4* hsrc = (const float4*)&g_hbuf[dir][buf][0][0];
        for (int i = tid; i < (B_DIM * U_DIM / 4); i += REC_THREADS) {
            float4 v = hsrc[i];
            int e = i * 4;
            *(float4*)&hs[(e >> 9) * HS_STRIDE + (e & 511)] = v;
        }

        const int tt = dir ? (T_SEQ - 1 - s) : s;
        float xg0[4], xg1[4];
        #pragma unroll
        for (int g = 0; g < 4; g++) {
            xg0[g] = g_xg[dir][b0][tt][g * U_DIM + ug];
            xg1[g] = g_xg[dir][b1][tt][g * U_DIM + ug];
        }
        __syncthreads();

        float acc0[4] = {0, 0, 0, 0}, acc1[4] = {0, 0, 0, 0};
        const float* h0p = hs + b0 * HS_STRIDE;
        const float* h1p = hs + b1 * HS_STRIDE;

        #pragma unroll 2
        for (int k = 0; k < U_DIM; k += 4) {
            const float4 h0v = *(const float4*)(h0p + k);
            const float4 h1v = *(const float4*)(h1p + k);
            const float4 u0v = *(const float4*)(up0 + k);
            const float4 u1v = *(const float4*)(up1 + k);
            const float4 u2v = *(const float4*)(up2 + k);
            const float4 u3v = *(const float4*)(up3 + k);
            acc0[0] = fmaf(h0v.x, u0v.x, fmaf(h0v.y, u0v.y, fmaf(h0v.z, u0v.z, fmaf(h0v.w, u0v.w, acc0[0]))));
            acc0[1] = fmaf(h0v.x, u1v.x, fmaf(h0v.y, u1v.y, fmaf(h0v.z, u1v.z, fmaf(h0v.w, u1v.w, acc0[1]))));
            acc0[2] = fmaf(h0v.x, u2v.x, fmaf(h0v.y, u2v.y, fmaf(h0v.z, u2v.z, fmaf(h0v.w, u2v.w, acc0[2]))));
            acc0[3] = fmaf(h0v.x, u3v.x, fmaf(h0v.y, u3v.y, fmaf(h0v.z, u3v.z, fmaf(h0v.w, u3v.w, acc0[3]))));
            acc1[0] = fmaf(h1v.x, u0v.x, fmaf(h1v.y, u0v.y, fmaf(h1v.z, u0v.z, fmaf(h1v.w, u0v.w, acc1[0]))));
            acc1[1] = fmaf(h1v.x, u1v.x, fmaf(h1v.y, u1v.y, fmaf(h1v.z, u1v.z, fmaf(h1v.w, u1v.w, acc1[1]))));
            acc1[2] = fmaf(h1v.x, u2v.x, fmaf(h1v.y, u2v.y, fmaf(h1v.z, u2v.z, fmaf(h1v.w, u2v.w, acc1[2]))));
            acc1[3] = fmaf(h1v.x, u3v.x, fmaf(h1v.y, u3v.y, fmaf(h1v.z, u3v.z, fmaf(h1v.w, u3v.w, acc1[3]))));
        }

        // gates (Keras order i, f, c, o)
        float i0 = sigm(xg0[0] + acc0[0]);
        float f0 = sigm(xg0[1] + acc0[1]);
        float g0 = tanhf(xg0[2] + acc0[2]);
        float o0 = sigm(xg0[3] + acc0[3]);
        c0s = f0 * c0s + i0 * g0;
        float h0 = o0 * tanhf(c0s);

        float i1 = sigm(xg1[0] + acc1[0]);
        float f1 = sigm(xg1[1] + acc1[1]);
        float g1 = tanhf(xg1[2] + acc1[2]);
        float o1 = sigm(xg1[3] + acc1[3]);
        c1s = f1 * c1s + i1 * g1;
        float h1 = o1 * tanhf(c1s);

        g_hbuf[dir][buf ^ 1][b0][ug] = h0;
        g_hbuf[dir][buf ^ 1][b1][ug] = h1;

        if (dir == 0) {
            out[((size_t)b0 * T_SEQ + s) * U_DIM + ug] = h0;
            out[((size_t)b1 * T_SEQ + s) * U_DIM + ug] = h1;
        } else {
            g_hb_out[b0][tt][ug] = h0;
            g_hb_out[b1][tt][ug] = h1;
        }

        gbar(++ep);
    }
}

// =================================================================================
// Kernel C: out += backward outputs
// =================================================================================
__global__ void add_bwd(float* __restrict__ out)
{
    int i = blockIdx.x * blockDim.x + threadIdx.x;
    const int n4 = B_DIM * T_SEQ * U_DIM / 4;
    if (i < n4) {
        float4 a = ((float4*)out)[i];
        float4 b = ((const float4*)&g_hb_out[0][0][0])[i];
        a.x += b.x; a.y += b.y; a.z += b.z; a.w += b.w;
        ((float4*)out)[i] = a;
    }
}

// =================================================================================
extern "C" void kernel_launch(void* const* d_in, const int* in_sizes, int n_in,
                              void* d_out, int out_size)
{
    const float* x  = (const float*)d_in[0];
    const float* z  = (const float*)d_in[1];
    const float* Wf = (const float*)d_in[2];
    const float* Uf = (const float*)d_in[3];
    const float* bf = (const float*)d_in[4];
    const float* Wb = (const float*)d_in[5];
    const float* Ub = (const float*)d_in[6];
    const float* bb = (const float*)d_in[7];
    float* out = (float*)d_out;

    cudaFuncSetAttribute(lstm_rec, cudaFuncAttributeMaxDynamicSharedMemorySize, SMEM_REC);

    dim3 gg(M_TOT / 128, NG / 128, 2);
    gemm_xg<<<gg, 256>>>(x, Wf, bf, Wb, bb);
    lstm_rec<<<NCTA, REC_THREADS, SMEM_REC>>>(z, Uf, Ub, out);
    add_bwd<<<(B_DIM * T_SEQ * U_DIM / 4 + 255) / 256, 256>>>(out);
}